// round 5
// baseline (speedup 1.0000x reference)
#include <cuda_runtime.h>
#include <cstdint>

// Problem constants
#define BS      16
#define C_TOT   512
#define HW      1024          // 32*32
#define N_TOT   16384         // BS*HW
#define M_SUB   8
#define NE      1024
#define E_DIM   64
// Tiling
#define TN      128           // n per block
#define KC      64            // codes per chunk
#define NCHUNK  (NE / KC)     // 16
#define ZS_STRIDE 68          // 64 + 4 pad (16B-aligned rows)
#define ES_STRIDE 68
// Output layout (float32, tuple-concatenated)
#define OUT_LOSS 8388608
#define OUT_IDX  8388609
#define OUT_BIN  (OUT_IDX + M_SUB * N_TOT)   // 8519681

typedef unsigned long long u64;

// Scratch (no cudaMalloc allowed)
__device__ int   g_idx[M_SUB * N_TOT];
__device__ float g_losspart[M_SUB * (N_TOT / TN)];   // 1024
__device__ int   g_bins[NE];

// smem bytes for argmin kernel: zs + es + enorm + znorm + lossbuf
#define SMEM_A_FLOATS (TN*ZS_STRIDE + KC*ES_STRIDE + KC + TN + TN)
#define SMEM_A_BYTES  (SMEM_A_FLOATS * 4)

// ---------------------------------------------------------------------------
// Kernel A: per (m, n-tile) nearest-code search + loss partials.
// CRITICAL for exactness vs the fp32 reference:
//   dist_k = fl( fl(||z||^2 + ||e_k||^2) - 2*(z.e_k) )
// The +||z||^2 quantizes distances to ulp(~64)=7.6e-6, creating ties that
// argmin must break by LOWEST index, exactly like jnp.argmin does.
// Register tile: 8 n x 4 k per thread, 256 threads -> 128 n x 64 k block tile.
// Dot products accumulated with packed fma.rn.f32x2 (pairs along d).
// ---------------------------------------------------------------------------
__global__ __launch_bounds__(256, 2)
void vq_argmin_kernel(const float* __restrict__ z, const float* __restrict__ cb)
{
    extern __shared__ float smem[];
    float* zs      = smem;                       // [TN][ZS_STRIDE]
    float* es      = zs + TN * ZS_STRIDE;        // [KC][ES_STRIDE]
    float* enorm   = es + KC * ES_STRIDE;        // [KC]
    float* znorm   = enorm + KC;                 // [TN]
    float* lossbuf = znorm + TN;                 // [TN]

    const int tid  = threadIdx.x;
    const int tx   = tid & 15;    // k direction (16)
    const int ty   = tid >> 4;    // n direction (16)
    const int m    = blockIdx.y;
    const int tile = blockIdx.x;
    const int n_base = tile * TN;
    const int b    = n_base >> 10;          // TN divides HW=1024
    const int hw0  = n_base & 1023;

    // zero the histogram bins (kernel B consumes them after A completes)
    if (blockIdx.x == 0 && blockIdx.y == 0) {
        for (int i = tid; i < NE; i += 256) g_bins[i] = 0;
    }

    // ---- load z tile transposed into zs[nl][d] ----
    const float* zsrc = z + (size_t)(b * C_TOT + m * E_DIM) * HW + hw0;
    for (int idx = tid; idx < E_DIM * TN; idx += 256) {
        int d  = idx >> 7;       // idx / 128
        int nl = idx & 127;
        zs[nl * ZS_STRIDE + d] = zsrc[(size_t)d * HW + nl];
    }
    __syncthreads();

    // per-n ||z||^2 (fp32; any summation order is safe — errors are exact
    // grid multiples of ulp(zn), which shift all candidate distances of a
    // row uniformly and preserve order + ties)
    if (tid < TN) {
        const float4* zr = reinterpret_cast<const float4*>(&zs[tid * ZS_STRIDE]);
        float s = 0.f;
        #pragma unroll
        for (int q = 0; q < 16; q++) {
            float4 v = zr[q];
            s += v.x * v.x + v.y * v.y + v.z * v.z + v.w * v.w;
        }
        znorm[tid] = s;
    }

    float bestv[8];
    int   besti[8];
    #pragma unroll
    for (int i = 0; i < 8; i++) { bestv[i] = 3.4e38f; besti[i] = 0; }

    const float4* cb4 = reinterpret_cast<const float4*>(cb + (size_t)m * NE * E_DIM);

    for (int ch = 0; ch < NCHUNK; ch++) {
        // ---- load codebook chunk: KC codes x 64 floats ----
        for (int idx4 = tid; idx4 < KC * 16; idx4 += 256) {
            int k  = idx4 >> 4;
            int d4 = idx4 & 15;
            float4 v = cb4[(ch * KC + k) * 16 + d4];
            *reinterpret_cast<float4*>(&es[k * ES_STRIDE + d4 * 4]) = v;
        }
        __syncthreads();  // sync A: es ready

        // per-code ||e||^2 (consumed after sync B)
        if (tid < KC) {
            const float4* er = reinterpret_cast<const float4*>(&es[tid * ES_STRIDE]);
            float s = 0.f;
            #pragma unroll
            for (int q = 0; q < 16; q++) {
                float4 v = er[q];
                s += v.x * v.x + v.y * v.y + v.z * v.z + v.w * v.w;
            }
            enorm[tid] = s;
        }

        // ---- mainloop: dot(z_n, e_k) for 8 n x 4 k, packed f32x2 along d ----
        u64 acc[8][4];
        #pragma unroll
        for (int i = 0; i < 8; i++)
            #pragma unroll
            for (int j = 0; j < 4; j++) acc[i][j] = 0ull;

        #pragma unroll
        for (int d4 = 0; d4 < 16; d4++) {
            ulonglong2 bv[4];
            #pragma unroll
            for (int j = 0; j < 4; j++)
                bv[j] = *reinterpret_cast<const ulonglong2*>(
                    &es[(j * 16 + tx) * ES_STRIDE + d4 * 4]);
            #pragma unroll
            for (int i = 0; i < 8; i++) {
                ulonglong2 av = *reinterpret_cast<const ulonglong2*>(
                    &zs[(i * 16 + ty) * ZS_STRIDE + d4 * 4]);
                #pragma unroll
                for (int j = 0; j < 4; j++) {
                    asm("fma.rn.f32x2 %0, %1, %2, %0;"
                        : "+l"(acc[i][j]) : "l"(av.x), "l"(bv[j].x));
                }
                #pragma unroll
                for (int j = 0; j < 4; j++) {
                    asm("fma.rn.f32x2 %0, %1, %2, %0;"
                        : "+l"(acc[i][j]) : "l"(av.y), "l"(bv[j].y));
                }
            }
        }
        __syncthreads();  // sync B: enorm ready, es free for next chunk

        // ---- chunk epilogue: quantized distances + running argmin ----
        float zn_r[8];
        #pragma unroll
        for (int i = 0; i < 8; i++) zn_r[i] = znorm[i * 16 + ty];

        #pragma unroll
        for (int j = 0; j < 4; j++) {
            int kl = j * 16 + tx;
            float en = enorm[kl];
            int  kg = ch * KC + kl;
            #pragma unroll
            for (int i = 0; i < 8; i++) {
                u64 a = acc[i][j];
                float lo = __uint_as_float((unsigned)a);
                float hi = __uint_as_float((unsigned)(a >> 32));
                float dot = __fadd_rn(lo, hi);
                // replicate reference rounding: fl(fl(zn+en) - 2*dot)
                float s    = __fadd_rn(zn_r[i], en);
                float dist = __fmaf_rn(-2.f, dot, s);   // 2*dot exact
                if (dist < bestv[i] || (dist == bestv[i] && kg < besti[i])) {
                    bestv[i] = dist; besti[i] = kg;
                }
            }
        }
    }

    // ---- reduce argmin across the 16 tx lanes (lowest index on ties) ----
    #pragma unroll
    for (int i = 0; i < 8; i++) {
        float v = bestv[i]; int bi = besti[i];
        #pragma unroll
        for (int off = 8; off >= 1; off >>= 1) {
            float ov = __shfl_xor_sync(0xffffffffu, v, off);
            int   oi = __shfl_xor_sync(0xffffffffu, bi, off);
            if (ov < v || (ov == v && oi < bi)) { v = ov; bi = oi; }
        }
        bestv[i] = v; besti[i] = bi;
    }

    if (tx == 0) {
        #pragma unroll
        for (int i = 0; i < 8; i++) {
            int nl = i * 16 + ty;
            g_idx[m * N_TOT + n_base + nl] = besti[i];
            // bestv = fl(||z||^2+||e||^2) - 2 z.e  ==  sum_d (e-z)^2
            lossbuf[nl] = bestv[i];
        }
    }
    __syncthreads();
    if (tid == 0) {
        float s = 0.f;
        for (int nl = 0; nl < TN; nl++) s += lossbuf[nl];
        g_losspart[m * (N_TOT / TN) + tile] = s;
    }
}

// ---------------------------------------------------------------------------
// Kernel B: gather chosen codes, apply straight-through rounding exactly as
// the reference (zq_st = fl(zf + fl(zq - zf))), scatter to NCHW, histogram.
// ---------------------------------------------------------------------------
__global__ __launch_bounds__(256)
void vq_scatter_kernel(const float* __restrict__ z, const float* __restrict__ cb,
                       float* __restrict__ out)
{
    __shared__ float cs[TN][ZS_STRIDE];
    __shared__ int   sidx[TN];

    const int tid  = threadIdx.x;
    const int m    = blockIdx.y;
    const int tile = blockIdx.x;
    const int n_base = tile * TN;
    const int b   = n_base >> 10;
    const int hw0 = n_base & 1023;

    if (tid < TN) {
        int v = g_idx[m * N_TOT + n_base + tid];
        sidx[tid] = v;
        atomicAdd(&g_bins[v], 1);
    }
    __syncthreads();

    const float4* cb4 = reinterpret_cast<const float4*>(cb + (size_t)m * NE * E_DIM);
    for (int idx4 = tid; idx4 < TN * 16; idx4 += 256) {
        int r  = idx4 >> 4;
        int d4 = idx4 & 15;
        float4 v = cb4[sidx[r] * 16 + d4];
        *reinterpret_cast<float4*>(&cs[r][d4 * 4]) = v;
    }
    __syncthreads();

    const float* zsrc = z   + (size_t)(b * C_TOT + m * E_DIM) * HW + hw0;
    float*       dst  = out + (size_t)(b * C_TOT + m * E_DIM) * HW + hw0;
    for (int idx = tid; idx < E_DIM * TN; idx += 256) {
        int d  = idx >> 7;
        int nl = idx & 127;
        size_t off = (size_t)d * HW + nl;
        float zv   = zsrc[off];
        float code = cs[nl][d];
        float t    = __fsub_rn(code, zv);     // fl(zq - zf)
        dst[off]   = __fadd_rn(zv, t);        // fl(zf + (zq - zf))
    }
}

// ---------------------------------------------------------------------------
// Kernel C: deterministic loss reduction + index/bin dtype conversion.
// ---------------------------------------------------------------------------
__global__ __launch_bounds__(256)
void vq_final_kernel(float* __restrict__ out)
{
    if (blockIdx.x == 0) {
        __shared__ float part[256];
        int tid = threadIdx.x;
        float s = 0.f;
        #pragma unroll
        for (int q = 0; q < 4; q++) s += g_losspart[tid * 4 + q];
        part[tid] = s;
        __syncthreads();
        if (tid == 0) {
            float t = 0.f;
            for (int q = 0; q < 256; q++) t += part[q];
            // loss = sum_m (1 + BETA) * mean_m = 1.25 / (N*64) * total
            out[OUT_LOSS] = t * (1.25f / (float)(N_TOT * E_DIM));
        }
    } else {
        int off = (blockIdx.x - 1) * 256 + threadIdx.x;
        if (off < M_SUB * N_TOT) {
            out[OUT_IDX + off] = (float)g_idx[off];
        } else {
            int bo = off - M_SUB * N_TOT;
            if (bo < NE) out[OUT_BIN + bo] = (float)g_bins[bo];
        }
    }
}

// ---------------------------------------------------------------------------
extern "C" void kernel_launch(void* const* d_in, const int* in_sizes, int n_in,
                              void* d_out, int out_size)
{
    const float* z  = (const float*)d_in[0];
    const float* cb = (const float*)d_in[1];
    float* out = (float*)d_out;

    cudaFuncSetAttribute(vq_argmin_kernel,
                         cudaFuncAttributeMaxDynamicSharedMemorySize, SMEM_A_BYTES);

    dim3 gridA(N_TOT / TN, M_SUB);   // 128 x 8
    vq_argmin_kernel<<<gridA, 256, SMEM_A_BYTES>>>(z, cb);

    dim3 gridB(N_TOT / TN, M_SUB);
    vq_scatter_kernel<<<gridB, 256>>>(z, cb, out);

    int conv_elems = M_SUB * N_TOT + NE;               // 132096
    int gridC = 1 + (conv_elems + 255) / 256;          // 517
    vq_final_kernel<<<gridC, 256>>>(out);
}

// round 8
// speedup vs baseline: 1.0417x; 1.0417x over previous
#include <cuda_runtime.h>
#include <cstdint>

// Problem constants
#define BS      16
#define C_TOT   512
#define HW      1024          // 32*32
#define N_TOT   16384         // BS*HW
#define M_SUB   8
#define NE      1024
#define E_DIM   64
// Tiling
#define TN      128           // n per block
#define KC      64            // codes per chunk
#define NCHUNK  (NE / KC)     // 16
#define ZS_STRIDE 68          // 64 + 4 pad (16B-aligned rows)
#define ES_STRIDE 68
// Output layout (float32, tuple-concatenated)
#define OUT_LOSS 8388608
#define OUT_IDX  8388609
#define OUT_BIN  (OUT_IDX + M_SUB * N_TOT)   // 8519681

typedef unsigned long long u64;

// Scratch (no cudaMalloc allowed)
__device__ int   g_idx[M_SUB * N_TOT];
__device__ float g_losspart[M_SUB * (N_TOT / TN)];   // 1024
__device__ int   g_bins[NE];

// smem floats: zs + 2*es + 2*enorm + znorm + lossbuf
#define SMEM_A_FLOATS (TN*ZS_STRIDE + 2*KC*ES_STRIDE + 2*KC + TN + TN)
#define SMEM_A_BYTES  (SMEM_A_FLOATS * 4)

__device__ __forceinline__ void cp_async16(uint32_t saddr, const void* gptr) {
    asm volatile("cp.async.cg.shared.global [%0], [%1], 16;"
                 :: "r"(saddr), "l"(gptr));
}
#define CP_COMMIT()  asm volatile("cp.async.commit_group;")
#define CP_WAIT(n)   asm volatile("cp.async.wait_group %0;" :: "n"(n))

// ---------------------------------------------------------------------------
// Kernel A: per (m, n-tile) nearest-code search + loss partials.
// Exactness vs the fp32 reference:
//   dist_k = fl( fl(||z||^2 + ||e_k||^2) - 2*(z.e_k) )
// quantizes distances to ulp(~64), creating ties that argmin breaks by
// LOWEST index (per-thread: ascending-k + strict <; cross-lane: explicit).
// Register tile: 8n x 4k per thread (256 thr -> 128n x 64k block tile),
// packed fma.rn.f32x2 along d. Codebook chunks are double-buffered via
// cp.async so the per-chunk global load overlaps the previous chunk's math.
// ---------------------------------------------------------------------------
__global__ __launch_bounds__(256, 2)
void vq_argmin_kernel(const float* __restrict__ z, const float* __restrict__ cb)
{
    extern __shared__ float smem[];
    float* zs      = smem;                         // [TN][ZS_STRIDE]
    float* es0     = zs   + TN * ZS_STRIDE;        // [KC][ES_STRIDE]
    float* es1     = es0  + KC * ES_STRIDE;        // [KC][ES_STRIDE]
    float* enorm0  = es1  + KC * ES_STRIDE;        // [KC]
    float* enorm1  = enorm0 + KC;                  // [KC]
    float* znorm   = enorm1 + KC;                  // [TN]
    float* lossbuf = znorm + TN;                   // [TN]

    float* esb[2]    = { es0, es1 };
    float* enormb[2] = { enorm0, enorm1 };
    uint32_t es_u32[2] = {
        (uint32_t)__cvta_generic_to_shared(es0),
        (uint32_t)__cvta_generic_to_shared(es1)
    };

    const int tid  = threadIdx.x;
    const int tx   = tid & 15;    // k direction (16)
    const int ty   = tid >> 4;    // n direction (16)
    const int m    = blockIdx.y;
    const int tile = blockIdx.x;
    const int n_base = tile * TN;
    const int b    = n_base >> 10;          // TN divides HW=1024
    const int hw0  = n_base & 1023;

    // zero the histogram bins (kernel B consumes them after A completes)
    if (blockIdx.x == 0 && blockIdx.y == 0) {
        for (int i = tid; i < NE; i += 256) g_bins[i] = 0;
    }

    const float4* cb4 = reinterpret_cast<const float4*>(cb + (size_t)m * NE * E_DIM);

    // ---- prologue: async-load codebook chunk 0 into buffer 0 ----
    {
        #pragma unroll
        for (int q = 0; q < 4; q++) {
            int idx4 = tid + q * 256;          // = k*16 + d4
            int k  = idx4 >> 4;
            int d4 = idx4 & 15;
            cp_async16(es_u32[0] + (uint32_t)(k * ES_STRIDE + d4 * 4) * 4,
                       cb4 + idx4);
        }
        CP_COMMIT();
    }

    // ---- load z tile transposed into zs[nl][d] ----
    const float* zsrc = z + (size_t)(b * C_TOT + m * E_DIM) * HW + hw0;
    for (int idx = tid; idx < E_DIM * TN; idx += 256) {
        int d  = idx >> 7;       // idx / 128
        int nl = idx & 127;
        zs[nl * ZS_STRIDE + d] = zsrc[(size_t)d * HW + nl];
    }
    __syncthreads();

    // per-n ||z||^2 (any order is fine: error is a grid-multiple shift common
    // to all candidates of the row, preserving order + ties)
    if (tid < TN) {
        const float4* zr = reinterpret_cast<const float4*>(&zs[tid * ZS_STRIDE]);
        float s = 0.f;
        #pragma unroll
        for (int q = 0; q < 16; q++) {
            float4 v = zr[q];
            s += v.x * v.x + v.y * v.y + v.z * v.z + v.w * v.w;
        }
        znorm[tid] = s;
    }
    __syncthreads();   // znorm visible to every thread

    // hoist this thread's 8 z-norms out of the chunk loop
    float zn_r[8];
    #pragma unroll
    for (int i = 0; i < 8; i++) zn_r[i] = znorm[i * 16 + ty];

    float bestv[8];
    int   besti[8];
    #pragma unroll
    for (int i = 0; i < 8; i++) { bestv[i] = 3.4e38f; besti[i] = 0; }

    int p = 0;
    for (int ch = 0; ch < NCHUNK; ch++) {
        // issue next chunk into the other buffer, then wait for this chunk
        if (ch + 1 < NCHUNK) {
            const float4* src = cb4 + (ch + 1) * (KC * 16);
            #pragma unroll
            for (int q = 0; q < 4; q++) {
                int idx4 = tid + q * 256;
                int k  = idx4 >> 4;
                int d4 = idx4 & 15;
                cp_async16(es_u32[p ^ 1] + (uint32_t)(k * ES_STRIDE + d4 * 4) * 4,
                           src + idx4);
            }
            CP_COMMIT();
            CP_WAIT(1);          // chunk ch complete (1 group may stay in flight)
        } else {
            CP_WAIT(0);
        }
        __syncthreads();         // sync A: es[p] visible to all warps

        float* es    = esb[p];
        float* enorm = enormb[p];

        // per-code ||e||^2 (consumed after sync B)
        if (tid < KC) {
            const float4* er = reinterpret_cast<const float4*>(&es[tid * ES_STRIDE]);
            float s = 0.f;
            #pragma unroll
            for (int q = 0; q < 16; q++) {
                float4 v = er[q];
                s += v.x * v.x + v.y * v.y + v.z * v.z + v.w * v.w;
            }
            enorm[tid] = s;
        }

        // ---- mainloop: dot(z_n, e_k) for 8 n x 4 k, packed f32x2 along d ----
        u64 acc[8][4];
        #pragma unroll
        for (int i = 0; i < 8; i++)
            #pragma unroll
            for (int j = 0; j < 4; j++) acc[i][j] = 0ull;

        #pragma unroll
        for (int d4 = 0; d4 < 16; d4++) {
            ulonglong2 bv[4];
            #pragma unroll
            for (int j = 0; j < 4; j++)
                bv[j] = *reinterpret_cast<const ulonglong2*>(
                    &es[(j * 16 + tx) * ES_STRIDE + d4 * 4]);
            #pragma unroll
            for (int i = 0; i < 8; i++) {
                ulonglong2 av = *reinterpret_cast<const ulonglong2*>(
                    &zs[(i * 16 + ty) * ZS_STRIDE + d4 * 4]);
                #pragma unroll
                for (int j = 0; j < 4; j++) {
                    asm("fma.rn.f32x2 %0, %1, %2, %0;"
                        : "+l"(acc[i][j]) : "l"(av.x), "l"(bv[j].x));
                }
                #pragma unroll
                for (int j = 0; j < 4; j++) {
                    asm("fma.rn.f32x2 %0, %1, %2, %0;"
                        : "+l"(acc[i][j]) : "l"(av.y), "l"(bv[j].y));
                }
            }
        }
        __syncthreads();  // sync B: enorm[p] ready; all warps done reading es[p]

        // ---- chunk epilogue: quantized distances + running argmin.
        // k ascending per thread + strict < == lowest-index tie-break. ----
        #pragma unroll
        for (int j = 0; j < 4; j++) {
            int kl = j * 16 + tx;
            float en = enorm[kl];
            int  kg = ch * KC + kl;
            #pragma unroll
            for (int i = 0; i < 8; i++) {
                u64 a = acc[i][j];
                float lo = __uint_as_float((unsigned)a);
                float hi = __uint_as_float((unsigned)(a >> 32));
                float dot = __fadd_rn(lo, hi);
                // replicate reference rounding: fl(fl(zn+en) - 2*dot)
                float s    = __fadd_rn(zn_r[i], en);
                float dist = __fmaf_rn(-2.f, dot, s);   // 2*dot exact
                if (dist < bestv[i]) { bestv[i] = dist; besti[i] = kg; }
            }
        }
        p ^= 1;
    }

    // ---- reduce argmin across the 16 tx lanes (lowest index on ties) ----
    #pragma unroll
    for (int i = 0; i < 8; i++) {
        float v = bestv[i]; int bi = besti[i];
        #pragma unroll
        for (int off = 8; off >= 1; off >>= 1) {
            float ov = __shfl_xor_sync(0xffffffffu, v, off);
            int   oi = __shfl_xor_sync(0xffffffffu, bi, off);
            if (ov < v || (ov == v && oi < bi)) { v = ov; bi = oi; }
        }
        bestv[i] = v; besti[i] = bi;
    }

    if (tx == 0) {
        #pragma unroll
        for (int i = 0; i < 8; i++) {
            int nl = i * 16 + ty;
            g_idx[m * N_TOT + n_base + nl] = besti[i];
            // bestv = fl(||z||^2+||e||^2) - 2 z.e  ==  sum_d (e-z)^2
            lossbuf[nl] = bestv[i];
        }
    }
    __syncthreads();
    if (tid == 0) {
        float s = 0.f;
        for (int nl = 0; nl < TN; nl++) s += lossbuf[nl];
        g_losspart[m * (N_TOT / TN) + tile] = s;
    }
}

// ---------------------------------------------------------------------------
// Kernel B: gather chosen codes, apply straight-through rounding exactly as
// the reference (zq_st = fl(zf + fl(zq - zf))), scatter to NCHW, histogram.
// ---------------------------------------------------------------------------
__global__ __launch_bounds__(256)
void vq_scatter_kernel(const float* __restrict__ z, const float* __restrict__ cb,
                       float* __restrict__ out)
{
    __shared__ float cs[TN][ZS_STRIDE];
    __shared__ int   sidx[TN];

    const int tid  = threadIdx.x;
    const int m    = blockIdx.y;
    const int tile = blockIdx.x;
    const int n_base = tile * TN;
    const int b   = n_base >> 10;
    const int hw0 = n_base & 1023;

    if (tid < TN) {
        int v = g_idx[m * N_TOT + n_base + tid];
        sidx[tid] = v;
        atomicAdd(&g_bins[v], 1);
    }
    __syncthreads();

    const float4* cb4 = reinterpret_cast<const float4*>(cb + (size_t)m * NE * E_DIM);
    for (int idx4 = tid; idx4 < TN * 16; idx4 += 256) {
        int r  = idx4 >> 4;
        int d4 = idx4 & 15;
        float4 v = cb4[sidx[r] * 16 + d4];
        *reinterpret_cast<float4*>(&cs[r][d4 * 4]) = v;
    }
    __syncthreads();

    const float* zsrc = z   + (size_t)(b * C_TOT + m * E_DIM) * HW + hw0;
    float*       dst  = out + (size_t)(b * C_TOT + m * E_DIM) * HW + hw0;
    for (int idx = tid; idx < E_DIM * TN; idx += 256) {
        int d  = idx >> 7;
        int nl = idx & 127;
        size_t off = (size_t)d * HW + nl;
        float zv   = zsrc[off];
        float code = cs[nl][d];
        float t    = __fsub_rn(code, zv);     // fl(zq - zf)
        dst[off]   = __fadd_rn(zv, t);        // fl(zf + (zq - zf))
    }
}

// ---------------------------------------------------------------------------
// Kernel C: deterministic loss reduction + index/bin dtype conversion.
// ---------------------------------------------------------------------------
__global__ __launch_bounds__(256)
void vq_final_kernel(float* __restrict__ out)
{
    if (blockIdx.x == 0) {
        __shared__ float part[256];
        int tid = threadIdx.x;
        float s = 0.f;
        #pragma unroll
        for (int q = 0; q < 4; q++) s += g_losspart[tid * 4 + q];
        part[tid] = s;
        __syncthreads();
        if (tid == 0) {
            float t = 0.f;
            for (int q = 0; q < 256; q++) t += part[q];
            // loss = sum_m (1 + BETA) * mean_m = 1.25 / (N*64) * total
            out[OUT_LOSS] = t * (1.25f / (float)(N_TOT * E_DIM));
        }
    } else {
        int off = (blockIdx.x - 1) * 256 + threadIdx.x;
        if (off < M_SUB * N_TOT) {
            out[OUT_IDX + off] = (float)g_idx[off];
        } else {
            int bo = off - M_SUB * N_TOT;
            if (bo < NE) out[OUT_BIN + bo] = (float)g_bins[bo];
        }
    }
}

// ---------------------------------------------------------------------------
extern "C" void kernel_launch(void* const* d_in, const int* in_sizes, int n_in,
                              void* d_out, int out_size)
{
    const float* z  = (const float*)d_in[0];
    const float* cb = (const float*)d_in[1];
    float* out = (float*)d_out;

    cudaFuncSetAttribute(vq_argmin_kernel,
                         cudaFuncAttributeMaxDynamicSharedMemorySize, SMEM_A_BYTES);

    dim3 gridA(N_TOT / TN, M_SUB);   // 128 x 8
    vq_argmin_kernel<<<gridA, 256, SMEM_A_BYTES>>>(z, cb);

    dim3 gridB(N_TOT / TN, M_SUB);
    vq_scatter_kernel<<<gridB, 256>>>(z, cb, out);

    int conv_elems = M_SUB * N_TOT + NE;               // 132096
    int gridC = 1 + (conv_elems + 255) / 256;          // 517
    vq_final_kernel<<<gridC, 256>>>(out);
}